// round 1
// baseline (speedup 1.0000x reference)
#include <cuda_runtime.h>
#include <math.h>

// ---------------- problem constants ----------------
#define BB   4
#define NNC  6          // cameras
#define CINC 512
#define CTC  64
#define FHC  16
#define FWC  44
#define DDC  41         // depth bins
#define PPI  (FHC*FWC)          // 704 pixels per image
#define NIMG (BB*NNC)           // 24
#define NPIX (NIMG*PPI)         // 16896
#define MPAD 112                // feat slots per pixel (105 rounded to 112)
#define NXXC 128
#define NYYC 128

// ---------------- scratch (device globals; no allocs allowed) ----------------
__device__ __align__(16) float g_WdT[512*128];      // [k][o], o zero-padded to 128
__device__ __align__(16) float g_bias[128];
__device__ __align__(16) float g_mats[NIMG*24];     // per image: invPost[9], comb[9], trans[3], postTrans[3]
__device__ __align__(16) float g_feat[NPIX*MPAD];
__device__ __align__(16) float g_depth[NPIX*DDC];
__device__ __align__(16) float g_cvt[NPIX*CTC];
__device__ __align__(16) int   g_vox[NPIX*DDC];
__device__ __align__(16) float g_bev[BB*NYYC*NXXC*CTC];   // [b][y][x][c]

// ---------------- 0: zero BEV accumulator ----------------
__global__ void k_zero()
{
    int i = blockIdx.x * 256 + threadIdx.x;          // 4096*256 = 1,048,576 float4
    reinterpret_cast<float4*>(g_bev)[i] = make_float4(0.f, 0.f, 0.f, 0.f);
}

// ---------------- 1: transpose + pad Wd, pad bias ----------------
__global__ void k_wdt(const float* __restrict__ Wd, const float* __restrict__ bd)
{
    int idx = blockIdx.x * 256 + threadIdx.x;        // 65536
    int k = idx >> 7, o = idx & 127;
    g_WdT[idx] = (o < 105) ? Wd[o * 512 + k] : 0.f;
    if (idx < 128) g_bias[idx] = (idx < 105) ? bd[idx] : 0.f;
}

// ---------------- 2: per-image matrices ----------------
__device__ __forceinline__ void inv3(const float* a, float* r)
{
    float det = a[0]*(a[4]*a[8]-a[5]*a[7])
              - a[1]*(a[3]*a[8]-a[5]*a[6])
              + a[2]*(a[3]*a[7]-a[4]*a[6]);
    float id = 1.0f / det;
    r[0] = (a[4]*a[8]-a[5]*a[7])*id;
    r[1] = (a[2]*a[7]-a[1]*a[8])*id;
    r[2] = (a[1]*a[5]-a[2]*a[4])*id;
    r[3] = (a[5]*a[6]-a[3]*a[8])*id;
    r[4] = (a[0]*a[8]-a[2]*a[6])*id;
    r[5] = (a[2]*a[3]-a[0]*a[5])*id;
    r[6] = (a[3]*a[7]-a[4]*a[6])*id;
    r[7] = (a[1]*a[6]-a[0]*a[7])*id;
    r[8] = (a[0]*a[4]-a[1]*a[3])*id;
}

__global__ void k_mats(const float* __restrict__ rots,  const float* __restrict__ trans,
                       const float* __restrict__ intrins, const float* __restrict__ post_rots,
                       const float* __restrict__ post_trans)
{
    int bn = threadIdx.x;
    if (bn >= NIMG) return;
    float P[9], Pi[9], K[9], Ki[9], R[9], C[9];
    #pragma unroll
    for (int i = 0; i < 9; i++) {
        P[i] = post_rots[bn*9 + i];
        K[i] = intrins[bn*9 + i];
        R[i] = rots[bn*9 + i];
    }
    inv3(P, Pi);
    inv3(K, Ki);
    #pragma unroll
    for (int i = 0; i < 3; i++)
        #pragma unroll
        for (int j = 0; j < 3; j++)
            C[i*3+j] = R[i*3+0]*Ki[0*3+j] + R[i*3+1]*Ki[1*3+j] + R[i*3+2]*Ki[2*3+j];
    float* m = &g_mats[bn*24];
    #pragma unroll
    for (int i = 0; i < 9; i++) { m[i] = Pi[i]; m[9+i] = C[i]; }
    #pragma unroll
    for (int i = 0; i < 3; i++) { m[18+i] = trans[bn*3+i]; m[21+i] = post_trans[bn*3+i]; }
}

// ---------------- 3: GEMM  feat[p][o] = sum_k X[k][p] * WdT[k][o]  ----------------
// block: 256 thr, tile M=128 (o), N=64 (pixels), K chunks of 32. grid = 24 imgs * 11 tiles.
__global__ __launch_bounds__(256) void k_gemm(const float* __restrict__ x)
{
    __shared__ float Xs[32][64];
    __shared__ float Ws[32][128];

    int img = blockIdx.x / 11;
    int p0  = (blockIdx.x % 11) * 64;
    const float* Ximg = x + (size_t)img * CINC * PPI;

    int tid = threadIdx.x;
    int tx = tid & 15;        // pixel group (4 px each)
    int ty = tid >> 4;        // o group (8 o each)

    float acc[8][4];
    #pragma unroll
    for (int i = 0; i < 8; i++)
        #pragma unroll
        for (int j = 0; j < 4; j++) acc[i][j] = 0.f;

    for (int k0 = 0; k0 < 512; k0 += 32) {
        // load X chunk: 32k x 64p = 512 float4
        #pragma unroll
        for (int j = 0; j < 2; j++) {
            int f = tid + j * 256;
            int k = f >> 4, pp = (f & 15) << 2;
            *reinterpret_cast<float4*>(&Xs[k][pp]) =
                *reinterpret_cast<const float4*>(&Ximg[(size_t)(k0 + k) * PPI + p0 + pp]);
        }
        // load W chunk: 32k x 128o = 1024 float4
        #pragma unroll
        for (int j = 0; j < 4; j++) {
            int f = tid + j * 256;
            int k = f >> 5, oo = (f & 31) << 2;
            *reinterpret_cast<float4*>(&Ws[k][oo]) =
                *reinterpret_cast<const float4*>(&g_WdT[(k0 + k) * 128 + oo]);
        }
        __syncthreads();
        #pragma unroll
        for (int k = 0; k < 32; k++) {
            float4 xv = *reinterpret_cast<float4*>(&Xs[k][tx << 2]);
            float4 wa = *reinterpret_cast<float4*>(&Ws[k][ty << 3]);
            float4 wb = *reinterpret_cast<float4*>(&Ws[k][(ty << 3) + 4]);
            float xr[4] = {xv.x, xv.y, xv.z, xv.w};
            float wr[8] = {wa.x, wa.y, wa.z, wa.w, wb.x, wb.y, wb.z, wb.w};
            #pragma unroll
            for (int i = 0; i < 8; i++)
                #pragma unroll
                for (int j = 0; j < 4; j++)
                    acc[i][j] = fmaf(wr[i], xr[j], acc[i][j]);
        }
        __syncthreads();
    }

    // epilogue: feat[p][o] = acc + bias. ty>=14 covers o>=112 (all zero pad) -> skip.
    if (ty < 14) {
        int gp0 = img * PPI + p0;
        float b0[8];
        #pragma unroll
        for (int i = 0; i < 8; i++) b0[i] = g_bias[(ty << 3) + i];
        #pragma unroll
        for (int j = 0; j < 4; j++) {
            int p = gp0 + (tx << 2) + j;
            float4 v0 = make_float4(acc[0][j] + b0[0], acc[1][j] + b0[1],
                                    acc[2][j] + b0[2], acc[3][j] + b0[3]);
            float4 v1 = make_float4(acc[4][j] + b0[4], acc[5][j] + b0[5],
                                    acc[6][j] + b0[6], acc[7][j] + b0[7]);
            *reinterpret_cast<float4*>(&g_feat[(size_t)p * MPAD + (ty << 3)])     = v0;
            *reinterpret_cast<float4*>(&g_feat[(size_t)p * MPAD + (ty << 3) + 4]) = v1;
        }
    }
}

// ---------------- 4: softmax over depth bins + copy cvt ----------------
__global__ void k_softmax()
{
    int p = blockIdx.x * 8 + (threadIdx.x >> 5);
    int l = threadIdx.x & 31;
    if (p >= NPIX) return;
    const float* f = &g_feat[(size_t)p * MPAD];

    float f0 = f[l];
    float f1 = (l < 9) ? f[32 + l] : -INFINITY;
    float m = fmaxf(f0, f1);
    #pragma unroll
    for (int o = 16; o; o >>= 1) m = fmaxf(m, __shfl_xor_sync(0xFFFFFFFFu, m, o));
    float e0 = __expf(f0 - m);
    float e1 = (l < 9) ? __expf(f1 - m) : 0.f;
    float s = e0 + e1;
    #pragma unroll
    for (int o = 16; o; o >>= 1) s += __shfl_xor_sync(0xFFFFFFFFu, s, o);
    float inv = 1.0f / s;
    g_depth[p * DDC + l] = e0 * inv;
    if (l < 9) g_depth[p * DDC + 32 + l] = e1 * inv;

    g_cvt[p * CTC + l]      = f[DDC + l];
    g_cvt[p * CTC + 32 + l] = f[DDC + 32 + l];
}

// ---------------- 5: geometry: point -> voxel id (or -1) ----------------
__global__ void k_geom()
{
    int idx = blockIdx.x * 256 + threadIdx.x;
    if (idx >= NPIX * DDC) return;
    int p  = idx / DDC;
    int d  = idx - p * DDC;
    int bn = p / PPI;
    int hw = p - bn * PPI;
    int h  = hw / FWC;
    int w  = hw - h * FWC;
    int b  = bn / NNC;

    const float* m = &g_mats[bn * 24];
    // frustum coords (match np.linspace computed in double)
    float xs = (float)((double)w * (703.0 / 43.0));
    float ys = (float)h * 17.0f;
    float zc = 4.0f + (float)d;

    float ax = xs - m[21], ay = ys - m[22], az = zc - m[23];
    float q0 = m[0]*ax + m[1]*ay + m[2]*az;
    float q1 = m[3]*ax + m[4]*ay + m[5]*az;
    float q2 = m[6]*ax + m[7]*ay + m[8]*az;
    float r0 = q0 * q2, r1 = q1 * q2, r2 = q2;
    float wx = m[9]*r0  + m[10]*r1 + m[11]*r2 + m[18];
    float wy = m[12]*r0 + m[13]*r1 + m[14]*r2 + m[19];
    float wz = m[15]*r0 + m[16]*r1 + m[17]*r2 + m[20];

    const float offx = -50.8f - 0.4f;   // BX - DX/2
    const float offz = 0.0f - 10.0f;
    int gx = (int)((wx - offx) / 0.8f);   // trunc toward zero == astype(int32)
    int gy = (int)((wy - offx) / 0.8f);
    int gz = (int)((wz - offz) / 20.0f);

    int vox = -1;
    if (gx >= 0 && gx < NXXC && gy >= 0 && gy < NYYC && gz == 0)
        vox = (b * NYYC + gy) * NXXC + gx;
    g_vox[idx] = vox;
}

// ---------------- 6: scatter-add into BEV (warp per pixel, lane = 2 channels) -------
__global__ void k_scatter()
{
    int p = blockIdx.x * 8 + (threadIdx.x >> 5);
    if (p >= NPIX) return;
    int l = threadIdx.x & 31;

    float2 cv = *reinterpret_cast<const float2*>(&g_cvt[(size_t)p * CTC + (l << 1)]);
    const int*   vp = &g_vox[p * DDC];
    const float* dp = &g_depth[p * DDC];

    for (int d = 0; d < DDC; d++) {
        int vox = __ldg(&vp[d]);
        if (vox >= 0) {
            float dep = __ldg(&dp[d]);
            float* dst = &g_bev[(size_t)vox * CTC + (l << 1)];
            atomicAdd(dst,     dep * cv.x);
            atomicAdd(dst + 1, dep * cv.y);
        }
    }
}

// ---------------- 7: transpose [b][y][x][c] -> out [b][c][y][x] ----------------
__global__ void k_transpose(float* __restrict__ out)
{
    __shared__ float t[32][33];
    int x0 = blockIdx.x * 32;            // 4 tiles
    int c0 = blockIdx.y * 32;            // 2 tiles
    int by = blockIdx.z;                 // b*128 + y  (512)
    int b  = by >> 7, y = by & 127;
    int tx = threadIdx.x, ty = threadIdx.y;   // 32 x 8

    const float* src = &g_bev[(size_t)by * NXXC * CTC];
    #pragma unroll
    for (int i = 0; i < 4; i++) {
        int xl = ty + i * 8;
        t[xl][tx] = src[(size_t)(x0 + xl) * CTC + c0 + tx];
    }
    __syncthreads();
    #pragma unroll
    for (int i = 0; i < 4; i++) {
        int cl = ty + i * 8;
        out[(((size_t)(b * CTC + c0 + cl) * NYYC) + y) * NXXC + x0 + tx] = t[tx][cl];
    }
}

// ---------------- launch ----------------
extern "C" void kernel_launch(void* const* d_in, const int* in_sizes, int n_in,
                              void* d_out, int out_size)
{
    const float* x          = (const float*)d_in[0];
    const float* rots       = (const float*)d_in[1];
    const float* trans      = (const float*)d_in[2];
    const float* intrins    = (const float*)d_in[3];
    const float* post_rots  = (const float*)d_in[4];
    const float* post_trans = (const float*)d_in[5];
    const float* Wd         = (const float*)d_in[6];
    const float* bd         = (const float*)d_in[7];
    float* out = (float*)d_out;

    k_zero<<<4096, 256>>>();
    k_wdt<<<256, 256>>>(Wd, bd);
    k_mats<<<1, 32>>>(rots, trans, intrins, post_rots, post_trans);
    k_gemm<<<NIMG * 11, 256>>>(x);
    k_softmax<<<NPIX / 8, 256>>>();
    k_geom<<<(NPIX * DDC + 255) / 256, 256>>>();
    k_scatter<<<NPIX / 8, 256>>>();
    k_transpose<<<dim3(4, 2, BB * NYYC), dim3(32, 8)>>>(out);
}

// round 2
// speedup vs baseline: 1.9020x; 1.9020x over previous
#include <cuda_runtime.h>
#include <math.h>
#include <stdint.h>

// ---------------- problem constants ----------------
#define BB   4
#define NNC  6          // cameras
#define CINC 512
#define CTC  64
#define FHC  16
#define FWC  44
#define DDC  41         // depth bins
#define PPI  (FHC*FWC)          // 704 pixels per image
#define NIMG (BB*NNC)           // 24
#define NPIX (NIMG*PPI)         // 16896
#define MPAD 112                // feat slots per pixel (105 rounded to 112)
#define NXXC 128
#define NYYC 128

// ---------------- scratch (device globals; no allocs allowed) ----------------
__device__ __align__(16) float g_WdT[512*112];      // [k][o], o zero-padded to 112
__device__ __align__(16) float g_bias[112];
__device__ __align__(16) float g_mats[NIMG*24];     // per image: invPost[9], comb[9], trans[3], postTrans[3]
__device__ __align__(16) float g_feat[NPIX*MPAD];
__device__ __align__(16) float g_depth[NPIX*DDC];
__device__ __align__(16) float g_cvt[NPIX*CTC];
__device__ __align__(16) int   g_vox[NPIX*DDC];
__device__ __align__(16) float g_bev[BB*NYYC*NXXC*CTC];   // [b][y][x][c]

// ---------------- async copy helpers ----------------
__device__ __forceinline__ void cpa16(uint32_t s, const void* g)
{
    asm volatile("cp.async.cg.shared.global [%0], [%1], 16;" :: "r"(s), "l"(g));
}
#define CP_COMMIT() asm volatile("cp.async.commit_group;")
#define CP_WAIT1()  asm volatile("cp.async.wait_group 1;")
#define CP_WAIT0()  asm volatile("cp.async.wait_group 0;")

// ---------------- 0: zero BEV accumulator ----------------
__global__ void k_zero()
{
    int i = blockIdx.x * 256 + threadIdx.x;          // 4096*256 = 1,048,576 float4
    reinterpret_cast<float4*>(g_bev)[i] = make_float4(0.f, 0.f, 0.f, 0.f);
}

// ---------------- 1: transpose + pad Wd, pad bias ----------------
__global__ void k_wdt(const float* __restrict__ Wd, const float* __restrict__ bd)
{
    int idx = blockIdx.x * 256 + threadIdx.x;        // 224*256 = 57344
    int k = idx / 112, o = idx - k * 112;
    g_WdT[idx] = (o < 105) ? Wd[o * 512 + k] : 0.f;
    if (idx < 112) g_bias[idx] = (idx < 105) ? bd[idx] : 0.f;
}

// ---------------- 2: per-image matrices ----------------
__device__ __forceinline__ void inv3(const float* a, float* r)
{
    float det = a[0]*(a[4]*a[8]-a[5]*a[7])
              - a[1]*(a[3]*a[8]-a[5]*a[6])
              + a[2]*(a[3]*a[7]-a[4]*a[6]);
    float id = 1.0f / det;
    r[0] = (a[4]*a[8]-a[5]*a[7])*id;
    r[1] = (a[2]*a[7]-a[1]*a[8])*id;
    r[2] = (a[1]*a[5]-a[2]*a[4])*id;
    r[3] = (a[5]*a[6]-a[3]*a[8])*id;
    r[4] = (a[0]*a[8]-a[2]*a[6])*id;
    r[5] = (a[2]*a[3]-a[0]*a[5])*id;
    r[6] = (a[3]*a[7]-a[4]*a[6])*id;
    r[7] = (a[1]*a[6]-a[0]*a[7])*id;
    r[8] = (a[0]*a[4]-a[1]*a[3])*id;
}

__global__ void k_mats(const float* __restrict__ rots,  const float* __restrict__ trans,
                       const float* __restrict__ intrins, const float* __restrict__ post_rots,
                       const float* __restrict__ post_trans)
{
    int bn = threadIdx.x;
    if (bn >= NIMG) return;
    float P[9], Pi[9], K[9], Ki[9], R[9], C[9];
    #pragma unroll
    for (int i = 0; i < 9; i++) {
        P[i] = post_rots[bn*9 + i];
        K[i] = intrins[bn*9 + i];
        R[i] = rots[bn*9 + i];
    }
    inv3(P, Pi);
    inv3(K, Ki);
    #pragma unroll
    for (int i = 0; i < 3; i++)
        #pragma unroll
        for (int j = 0; j < 3; j++)
            C[i*3+j] = R[i*3+0]*Ki[0*3+j] + R[i*3+1]*Ki[1*3+j] + R[i*3+2]*Ki[2*3+j];
    float* m = &g_mats[bn*24];
    #pragma unroll
    for (int i = 0; i < 9; i++) { m[i] = Pi[i]; m[9+i] = C[i]; }
    #pragma unroll
    for (int i = 0; i < 3; i++) { m[18+i] = trans[bn*3+i]; m[21+i] = post_trans[bn*3+i]; }
}

// ---------------- 3: GEMM  feat[p][o] = sum_k X[k][p] * WdT[k][o]  ----------------
// block: 224 thr, tile M=112 (o), N=64 (pixels), K chunks of 32, double-buffered cp.async.
// grid = 24 imgs * 11 tiles.
__global__ __launch_bounds__(224) void k_gemm(const float* __restrict__ x)
{
    __shared__ float Xs[2][32][64];     // 16 KB
    __shared__ float Ws[2][32][112];    // 28 KB

    int img = blockIdx.x / 11;
    int p0  = (blockIdx.x % 11) * 64;
    const float* Ximg = x + (size_t)img * CINC * PPI;

    int tid = threadIdx.x;
    int tx = tid & 15;        // pixel group (4 px each)
    int ty = tid >> 4;        // o group (8 o each), 0..13

    uint32_t sX = (uint32_t)__cvta_generic_to_shared(&Xs[0][0][0]);
    uint32_t sW = (uint32_t)__cvta_generic_to_shared(&Ws[0][0][0]);

    float acc[8][4];
    #pragma unroll
    for (int i = 0; i < 8; i++)
        #pragma unroll
        for (int j = 0; j < 4; j++) acc[i][j] = 0.f;

    // prefetch chunk 0
    {
        for (int i = tid; i < 512; i += 224) {            // X: 32k x 64p / 4
            int k = i >> 4, pp = (i & 15) << 2;
            cpa16(sX + (uint32_t)((k * 64 + pp) * 4),
                  &Ximg[(size_t)k * PPI + p0 + pp]);
        }
        for (int i = tid; i < 896; i += 224) {            // W: 32k x 112o / 4
            int k = i / 28, oo = (i - k * 28) << 2;
            cpa16(sW + (uint32_t)((k * 112 + oo) * 4),
                  &g_WdT[k * 112 + oo]);
        }
        CP_COMMIT();
    }

    for (int c = 0; c < 16; c++) {
        int buf = c & 1;
        if (c < 15) {
            int nb = (c + 1) & 1;
            int k0 = (c + 1) * 32;
            for (int i = tid; i < 512; i += 224) {
                int k = i >> 4, pp = (i & 15) << 2;
                cpa16(sX + (uint32_t)(((nb * 32 + k) * 64 + pp) * 4),
                      &Ximg[(size_t)(k0 + k) * PPI + p0 + pp]);
            }
            for (int i = tid; i < 896; i += 224) {
                int k = i / 28, oo = (i - k * 28) << 2;
                cpa16(sW + (uint32_t)(((nb * 32 + k) * 112 + oo) * 4),
                      &g_WdT[(k0 + k) * 112 + oo]);
            }
            CP_COMMIT();
            CP_WAIT1();
        } else {
            CP_WAIT0();
        }
        __syncthreads();

        #pragma unroll
        for (int k = 0; k < 32; k++) {
            float4 xv = *reinterpret_cast<float4*>(&Xs[buf][k][tx << 2]);
            float4 wa = *reinterpret_cast<float4*>(&Ws[buf][k][ty << 3]);
            float4 wb = *reinterpret_cast<float4*>(&Ws[buf][k][(ty << 3) + 4]);
            float xr[4] = {xv.x, xv.y, xv.z, xv.w};
            float wr[8] = {wa.x, wa.y, wa.z, wa.w, wb.x, wb.y, wb.z, wb.w};
            #pragma unroll
            for (int i = 0; i < 8; i++)
                #pragma unroll
                for (int j = 0; j < 4; j++)
                    acc[i][j] = fmaf(wr[i], xr[j], acc[i][j]);
        }
        __syncthreads();
    }

    // epilogue: feat[p][o] = acc + bias (o = 0..111)
    {
        int gp0 = img * PPI + p0;
        float b0[8];
        #pragma unroll
        for (int i = 0; i < 8; i++) b0[i] = g_bias[(ty << 3) + i];
        #pragma unroll
        for (int j = 0; j < 4; j++) {
            int p = gp0 + (tx << 2) + j;
            float4 v0 = make_float4(acc[0][j] + b0[0], acc[1][j] + b0[1],
                                    acc[2][j] + b0[2], acc[3][j] + b0[3]);
            float4 v1 = make_float4(acc[4][j] + b0[4], acc[5][j] + b0[5],
                                    acc[6][j] + b0[6], acc[7][j] + b0[7]);
            *reinterpret_cast<float4*>(&g_feat[(size_t)p * MPAD + (ty << 3)])     = v0;
            *reinterpret_cast<float4*>(&g_feat[(size_t)p * MPAD + (ty << 3) + 4]) = v1;
        }
    }
}

// ---------------- 4: softmax over depth bins + copy cvt ----------------
__global__ void k_softmax()
{
    int p = blockIdx.x * 8 + (threadIdx.x >> 5);
    int l = threadIdx.x & 31;
    if (p >= NPIX) return;
    const float* f = &g_feat[(size_t)p * MPAD];

    float f0 = f[l];
    float f1 = (l < 9) ? f[32 + l] : -INFINITY;
    float m = fmaxf(f0, f1);
    #pragma unroll
    for (int o = 16; o; o >>= 1) m = fmaxf(m, __shfl_xor_sync(0xFFFFFFFFu, m, o));
    float e0 = __expf(f0 - m);
    float e1 = (l < 9) ? __expf(f1 - m) : 0.f;
    float s = e0 + e1;
    #pragma unroll
    for (int o = 16; o; o >>= 1) s += __shfl_xor_sync(0xFFFFFFFFu, s, o);
    float inv = 1.0f / s;
    g_depth[p * DDC + l] = e0 * inv;
    if (l < 9) g_depth[p * DDC + 32 + l] = e1 * inv;

    g_cvt[p * CTC + l]      = f[DDC + l];
    g_cvt[p * CTC + 32 + l] = f[DDC + 32 + l];
}

// ---------------- 5: geometry: point -> voxel id (or -1) ----------------
__global__ void k_geom()
{
    int idx = blockIdx.x * 256 + threadIdx.x;
    if (idx >= NPIX * DDC) return;
    int p  = idx / DDC;
    int d  = idx - p * DDC;
    int bn = p / PPI;
    int hw = p - bn * PPI;
    int h  = hw / FWC;
    int w  = hw - h * FWC;
    int b  = bn / NNC;

    const float* m = &g_mats[bn * 24];
    float xs = (float)((double)w * (703.0 / 43.0));
    float ys = (float)h * 17.0f;
    float zc = 4.0f + (float)d;

    float ax = xs - m[21], ay = ys - m[22], az = zc - m[23];
    float q0 = m[0]*ax + m[1]*ay + m[2]*az;
    float q1 = m[3]*ax + m[4]*ay + m[5]*az;
    float q2 = m[6]*ax + m[7]*ay + m[8]*az;
    float r0 = q0 * q2, r1 = q1 * q2, r2 = q2;
    float wx = m[9]*r0  + m[10]*r1 + m[11]*r2 + m[18];
    float wy = m[12]*r0 + m[13]*r1 + m[14]*r2 + m[19];
    float wz = m[15]*r0 + m[16]*r1 + m[17]*r2 + m[20];

    const float offx = -50.8f - 0.4f;   // BX - DX/2
    const float offz = 0.0f - 10.0f;
    int gx = (int)((wx - offx) / 0.8f);
    int gy = (int)((wy - offx) / 0.8f);
    int gz = (int)((wz - offz) / 20.0f);

    int vox = -1;
    if (gx >= 0 && gx < NXXC && gy >= 0 && gy < NYYC && gz == 0)
        vox = (b * NYYC + gy) * NXXC + gx;
    g_vox[idx] = vox;
}

// ---------------- 6: scatter-add into BEV (half-warp per pixel, vector RED) -------
__global__ void k_scatter()
{
    int p = blockIdx.x * 16 + (threadIdx.x >> 4);   // 16 pixels per 256-thr block
    int l = threadIdx.x & 15;                        // lane -> 4 channels

    float4 cv = *reinterpret_cast<const float4*>(&g_cvt[(size_t)p * CTC + (l << 2)]);
    const int*   vp = &g_vox[p * DDC];
    const float* dp = &g_depth[p * DDC];

    for (int d = 0; d < DDC; d++) {
        int vox = __ldg(&vp[d]);
        if (vox >= 0) {
            float dep = __ldg(&dp[d]);
            float* dst = &g_bev[(size_t)vox * CTC + (l << 2)];
            asm volatile("red.global.add.v4.f32 [%0], {%1, %2, %3, %4};"
                         :: "l"(dst), "f"(dep * cv.x), "f"(dep * cv.y),
                            "f"(dep * cv.z), "f"(dep * cv.w)
                         : "memory");
        }
    }
}

// ---------------- 7: transpose [b][y][x][c] -> out [b][c][y][x] ----------------
__global__ void k_transpose(float* __restrict__ out)
{
    __shared__ float t[32][33];
    int x0 = blockIdx.x * 32;            // 4 tiles
    int c0 = blockIdx.y * 32;            // 2 tiles
    int by = blockIdx.z;                 // b*128 + y  (512)
    int b  = by >> 7, y = by & 127;
    int tx = threadIdx.x, ty = threadIdx.y;   // 32 x 8

    const float* src = &g_bev[(size_t)by * NXXC * CTC];
    #pragma unroll
    for (int i = 0; i < 4; i++) {
        int xl = ty + i * 8;
        t[xl][tx] = src[(size_t)(x0 + xl) * CTC + c0 + tx];
    }
    __syncthreads();
    #pragma unroll
    for (int i = 0; i < 4; i++) {
        int cl = ty + i * 8;
        out[(((size_t)(b * CTC + c0 + cl) * NYYC) + y) * NXXC + x0 + tx] = t[tx][cl];
    }
}

// ---------------- launch ----------------
extern "C" void kernel_launch(void* const* d_in, const int* in_sizes, int n_in,
                              void* d_out, int out_size)
{
    const float* x          = (const float*)d_in[0];
    const float* rots       = (const float*)d_in[1];
    const float* trans      = (const float*)d_in[2];
    const float* intrins    = (const float*)d_in[3];
    const float* post_rots  = (const float*)d_in[4];
    const float* post_trans = (const float*)d_in[5];
    const float* Wd         = (const float*)d_in[6];
    const float* bd         = (const float*)d_in[7];
    float* out = (float*)d_out;

    k_zero<<<4096, 256>>>();
    k_wdt<<<224, 256>>>(Wd, bd);
    k_mats<<<1, 32>>>(rots, trans, intrins, post_rots, post_trans);
    k_gemm<<<NIMG * 11, 224>>>(x);
    k_softmax<<<NPIX / 8, 256>>>();
    k_geom<<<(NPIX * DDC + 255) / 256, 256>>>();
    k_scatter<<<NPIX / 16, 256>>>();
    k_transpose<<<dim3(4, 2, BB * NYYC), dim3(32, 8)>>>(out);
}

// round 3
// speedup vs baseline: 2.3444x; 1.2326x over previous
#include <cuda_runtime.h>
#include <math.h>
#include <stdint.h>

typedef unsigned long long u64;

// ---------------- problem constants ----------------
#define BB   4
#define NNC  6
#define CINC 512
#define CTC  64
#define FHC  16
#define FWC  44
#define DDC  41
#define PPI  (FHC*FWC)          // 704
#define NIMG (BB*NNC)           // 24
#define NPIX (NIMG*PPI)         // 16896
#define MPAD 112
#define NXXC 128
#define NYYC 128

// ---------------- scratch ----------------
__device__ __align__(16) float g_WdT[512*112];
__device__ __align__(16) float g_bias[112];
__device__ __align__(16) float g_mats[NIMG*24];
__device__ __align__(16) float g_feat[NPIX*MPAD];
__device__ __align__(16) float g_bev[BB*NYYC*NXXC*CTC];   // [b][y][x][c]

// ---------------- helpers ----------------
__device__ __forceinline__ void cpa16(uint32_t s, const void* g)
{
    asm volatile("cp.async.cg.shared.global [%0], [%1], 16;" :: "r"(s), "l"(g));
}
#define CP_COMMIT() asm volatile("cp.async.commit_group;")
#define CP_WAIT1()  asm volatile("cp.async.wait_group 1;")
#define CP_WAIT0()  asm volatile("cp.async.wait_group 0;")

__device__ __forceinline__ u64 ffma2(u64 a, u64 b, u64 c)
{
    u64 d;
    asm("fma.rn.f32x2 %0, %1, %2, %3;" : "=l"(d) : "l"(a), "l"(b), "l"(c));
    return d;
}
__device__ __forceinline__ u64 bcast2(float x)
{
    u64 d;
    asm("mov.b64 %0, {%1, %1};" : "=l"(d) : "f"(x));
    return d;
}

__device__ __forceinline__ void inv3(const float* a, float* r)
{
    float det = a[0]*(a[4]*a[8]-a[5]*a[7])
              - a[1]*(a[3]*a[8]-a[5]*a[6])
              + a[2]*(a[3]*a[7]-a[4]*a[6]);
    float id = 1.0f / det;
    r[0] = (a[4]*a[8]-a[5]*a[7])*id;
    r[1] = (a[2]*a[7]-a[1]*a[8])*id;
    r[2] = (a[1]*a[5]-a[2]*a[4])*id;
    r[3] = (a[5]*a[6]-a[3]*a[8])*id;
    r[4] = (a[0]*a[8]-a[2]*a[6])*id;
    r[5] = (a[2]*a[3]-a[0]*a[5])*id;
    r[6] = (a[3]*a[7]-a[4]*a[6])*id;
    r[7] = (a[1]*a[6]-a[0]*a[7])*id;
    r[8] = (a[0]*a[4]-a[1]*a[3])*id;
}

// ---------------- prep: zero BEV + Wd transpose/pad + per-image mats ----------------
__global__ void k_prep(const float* __restrict__ Wd, const float* __restrict__ bd,
                       const float* __restrict__ rots, const float* __restrict__ trans,
                       const float* __restrict__ intrins, const float* __restrict__ post_rots,
                       const float* __restrict__ post_trans)
{
    int bi = blockIdx.x;
    int tid = threadIdx.x;
    if (bi < 4096) {                               // zero BEV: 4096*256 float4
        reinterpret_cast<float4*>(g_bev)[bi * 256 + tid] = make_float4(0.f,0.f,0.f,0.f);
    } else if (bi < 4320) {                        // WdT: 224*256 = 57344
        int idx = (bi - 4096) * 256 + tid;
        int k = idx / 112, o = idx - k * 112;
        g_WdT[idx] = (o < 105) ? Wd[o * 512 + k] : 0.f;
        if (idx < 112) g_bias[idx] = (idx < 105) ? bd[idx] : 0.f;
    } else {                                       // mats
        int bn = tid;
        if (bn >= NIMG) return;
        float P[9], Pi[9], K[9], Ki[9], R[9], C[9];
        #pragma unroll
        for (int i = 0; i < 9; i++) {
            P[i] = post_rots[bn*9 + i];
            K[i] = intrins[bn*9 + i];
            R[i] = rots[bn*9 + i];
        }
        inv3(P, Pi);
        inv3(K, Ki);
        #pragma unroll
        for (int i = 0; i < 3; i++)
            #pragma unroll
            for (int j = 0; j < 3; j++)
                C[i*3+j] = R[i*3+0]*Ki[0*3+j] + R[i*3+1]*Ki[1*3+j] + R[i*3+2]*Ki[2*3+j];
        float* m = &g_mats[bn*24];
        #pragma unroll
        for (int i = 0; i < 9; i++) { m[i] = Pi[i]; m[9+i] = C[i]; }
        #pragma unroll
        for (int i = 0; i < 3; i++) { m[18+i] = trans[bn*3+i]; m[21+i] = post_trans[bn*3+i]; }
    }
}

// ---------------- GEMM  feat[p][o] = sum_k X[k][p] * WdT[k][o]  (f32x2 packed) ------
// block 224 thr, tile M=112(o) x N=64(px), K chunks 32, double-buffered cp.async.
__global__ __launch_bounds__(224) void k_gemm(const float* __restrict__ x)
{
    __shared__ float Xs[2][32][64];     // 16 KB
    __shared__ float Ws[2][32][112];    // 28 KB

    int img = blockIdx.x / 11;
    int p0  = (blockIdx.x % 11) * 64;
    const float* Ximg = x + (size_t)img * CINC * PPI;

    int tid = threadIdx.x;
    int tx = tid & 15;        // pixel group (4 px)
    int ty = tid >> 4;        // o group (8 o = 4 pairs), 0..13

    uint32_t sX = (uint32_t)__cvta_generic_to_shared(&Xs[0][0][0]);
    uint32_t sW = (uint32_t)__cvta_generic_to_shared(&Ws[0][0][0]);

    u64 acc2[4][4];           // [o-pair][pixel], each holds (o_even, o_odd)
    #pragma unroll
    for (int i = 0; i < 4; i++)
        #pragma unroll
        for (int j = 0; j < 4; j++) acc2[i][j] = 0ull;

    // prefetch chunk 0
    for (int i = tid; i < 512; i += 224) {
        int k = i >> 4, pp = (i & 15) << 2;
        cpa16(sX + (uint32_t)((k * 64 + pp) * 4), &Ximg[(size_t)k * PPI + p0 + pp]);
    }
    for (int i = tid; i < 896; i += 224) {
        int k = i / 28, oo = (i - k * 28) << 2;
        cpa16(sW + (uint32_t)((k * 112 + oo) * 4), &g_WdT[k * 112 + oo]);
    }
    CP_COMMIT();

    for (int c = 0; c < 16; c++) {
        int buf = c & 1;
        if (c < 15) {
            int nb = (c + 1) & 1;
            int k0 = (c + 1) * 32;
            for (int i = tid; i < 512; i += 224) {
                int k = i >> 4, pp = (i & 15) << 2;
                cpa16(sX + (uint32_t)(((nb * 32 + k) * 64 + pp) * 4),
                      &Ximg[(size_t)(k0 + k) * PPI + p0 + pp]);
            }
            for (int i = tid; i < 896; i += 224) {
                int k = i / 28, oo = (i - k * 28) << 2;
                cpa16(sW + (uint32_t)(((nb * 32 + k) * 112 + oo) * 4),
                      &g_WdT[(k0 + k) * 112 + oo]);
            }
            CP_COMMIT();
            CP_WAIT1();
        } else {
            CP_WAIT0();
        }
        __syncthreads();

        #pragma unroll
        for (int k = 0; k < 32; k++) {
            float4 xv = *reinterpret_cast<float4*>(&Xs[buf][k][tx << 2]);
            ulonglong2 wa = *reinterpret_cast<ulonglong2*>(&Ws[buf][k][ty << 3]);
            ulonglong2 wb = *reinterpret_cast<ulonglong2*>(&Ws[buf][k][(ty << 3) + 4]);
            u64 wp[4] = {wa.x, wa.y, wb.x, wb.y};
            u64 xb[4] = {bcast2(xv.x), bcast2(xv.y), bcast2(xv.z), bcast2(xv.w)};
            #pragma unroll
            for (int i = 0; i < 4; i++)
                #pragma unroll
                for (int j = 0; j < 4; j++)
                    acc2[i][j] = ffma2(wp[i], xb[j], acc2[i][j]);
        }
        __syncthreads();
    }

    // epilogue: feat[p][o] = acc + bias (o = 0..111)
    {
        int gp0 = img * PPI + p0;
        float b0[8];
        #pragma unroll
        for (int i = 0; i < 8; i++) b0[i] = g_bias[(ty << 3) + i];
        #pragma unroll
        for (int j = 0; j < 4; j++) {
            int p = gp0 + (tx << 2) + j;
            float2 f0 = *reinterpret_cast<float2*>(&acc2[0][j]);
            float2 f1 = *reinterpret_cast<float2*>(&acc2[1][j]);
            float2 f2 = *reinterpret_cast<float2*>(&acc2[2][j]);
            float2 f3 = *reinterpret_cast<float2*>(&acc2[3][j]);
            float4 v0 = make_float4(f0.x + b0[0], f0.y + b0[1], f1.x + b0[2], f1.y + b0[3]);
            float4 v1 = make_float4(f2.x + b0[4], f2.y + b0[5], f3.x + b0[6], f3.y + b0[7]);
            *reinterpret_cast<float4*>(&g_feat[(size_t)p * MPAD + (ty << 3)])     = v0;
            *reinterpret_cast<float4*>(&g_feat[(size_t)p * MPAD + (ty << 3) + 4]) = v1;
        }
    }
}

// ---------------- fused pixel kernel: softmax + geometry + scatter ----------------
// warp per pixel; 8 warps/block.
__global__ __launch_bounds__(256) void k_pixel()
{
    __shared__ float scvt[8][64];
    __shared__ float sdep[8][48];
    __shared__ int   svox[8][48];

    int wpb = threadIdx.x >> 5;
    int p = blockIdx.x * 8 + wpb;
    int l = threadIdx.x & 31;

    const float* f = &g_feat[(size_t)p * MPAD];

    // softmax over 41 depth logits
    float f0 = f[l];
    float f1 = (l < 9) ? f[32 + l] : -INFINITY;
    float m = fmaxf(f0, f1);
    #pragma unroll
    for (int o = 16; o; o >>= 1) m = fmaxf(m, __shfl_xor_sync(0xFFFFFFFFu, m, o));
    float e0 = __expf(f0 - m);
    float e1 = (l < 9) ? __expf(f1 - m) : 0.f;
    float s = e0 + e1;
    #pragma unroll
    for (int o = 16; o; o >>= 1) s += __shfl_xor_sync(0xFFFFFFFFu, s, o);
    float inv = 1.0f / s;
    float dep0 = e0 * inv;
    float dep1 = e1 * inv;

    // context features to smem
    scvt[wpb][l]      = f[DDC + l];
    scvt[wpb][32 + l] = f[DDC + 32 + l];

    // geometry
    int bn = p / PPI;
    int hw = p - bn * PPI;
    int h  = hw / FWC;
    int w  = hw - h * FWC;
    int b  = bn / NNC;

    const float* mm = &g_mats[bn * 24];
    float xs = (float)((double)w * (703.0 / 43.0));
    float ys = (float)h * 17.0f;

    float ax = xs - mm[21], ay = ys - mm[22];
    float qb0 = mm[0]*ax + mm[1]*ay;
    float qb1 = mm[3]*ax + mm[4]*ay;
    float qb2 = mm[6]*ax + mm[7]*ay;

    const float offx = -50.8f - 0.4f;
    const float offz = 0.0f - 10.0f;

    #pragma unroll
    for (int pass = 0; pass < 2; pass++) {
        int d = pass ? (32 + l) : l;
        if (pass && l >= 9) {
            if (l < 16) { svox[wpb][32 + l] = -1; sdep[wpb][32 + l] = 0.f; } // pad 41..47
            break;
        }
        float az = (4.0f + (float)d) - mm[23];
        float q0 = qb0 + mm[2]*az;
        float q1 = qb1 + mm[5]*az;
        float q2 = qb2 + mm[8]*az;
        float r0 = q0 * q2, r1 = q1 * q2, r2 = q2;
        float wx = mm[9]*r0  + mm[10]*r1 + mm[11]*r2 + mm[18];
        float wy = mm[12]*r0 + mm[13]*r1 + mm[14]*r2 + mm[19];
        float wz = mm[15]*r0 + mm[16]*r1 + mm[17]*r2 + mm[20];
        int gx = (int)((wx - offx) / 0.8f);
        int gy = (int)((wy - offx) / 0.8f);
        int gz = (int)((wz - offz) / 20.0f);
        int vox = -1;
        if (gx >= 0 && gx < NXXC && gy >= 0 && gy < NYYC && gz == 0)
            vox = (b * NYYC + gy) * NXXC + gx;
        svox[wpb][d] = vox;
        sdep[wpb][d] = pass ? dep1 : dep0;
    }
    __syncwarp();

    // scatter: half-warp = one depth, lane quad = 4 channels
    float4 cv = *reinterpret_cast<float4*>(&scvt[wpb][(l & 15) << 2]);
    int half = l >> 4;
    #pragma unroll 4
    for (int it = 0; it < 21; it++) {
        int d = it * 2 + half;                 // 0..41 (41 padded to -1)
        int vox = svox[wpb][d];
        if (vox >= 0) {
            float dep = sdep[wpb][d];
            float* dst = &g_bev[(size_t)vox * CTC + ((l & 15) << 2)];
            asm volatile("red.global.add.v4.f32 [%0], {%1, %2, %3, %4};"
                         :: "l"(dst), "f"(dep * cv.x), "f"(dep * cv.y),
                            "f"(dep * cv.z), "f"(dep * cv.w)
                         : "memory");
        }
    }
}

// ---------------- transpose [b][y][x][c] -> out [b][c][y][x] ----------------
__global__ void k_transpose(float* __restrict__ out)
{
    __shared__ float t[32][33];
    int x0 = blockIdx.x * 32;
    int c0 = blockIdx.y * 32;
    int by = blockIdx.z;                 // b*128 + y
    int b  = by >> 7, y = by & 127;
    int tx = threadIdx.x, ty = threadIdx.y;

    const float* src = &g_bev[(size_t)by * NXXC * CTC];
    #pragma unroll
    for (int i = 0; i < 4; i++) {
        int xl = ty + i * 8;
        t[xl][tx] = src[(size_t)(x0 + xl) * CTC + c0 + tx];
    }
    __syncthreads();
    #pragma unroll
    for (int i = 0; i < 4; i++) {
        int cl = ty + i * 8;
        out[(((size_t)(b * CTC + c0 + cl) * NYYC) + y) * NXXC + x0 + tx] = t[tx][cl];
    }
}

// ---------------- launch ----------------
extern "C" void kernel_launch(void* const* d_in, const int* in_sizes, int n_in,
                              void* d_out, int out_size)
{
    const float* x          = (const float*)d_in[0];
    const float* rots       = (const float*)d_in[1];
    const float* trans      = (const float*)d_in[2];
    const float* intrins    = (const float*)d_in[3];
    const float* post_rots  = (const float*)d_in[4];
    const float* post_trans = (const float*)d_in[5];
    const float* Wd         = (const float*)d_in[6];
    const float* bd         = (const float*)d_in[7];
    float* out = (float*)d_out;

    k_prep<<<4321, 256>>>(Wd, bd, rots, trans, intrins, post_rots, post_trans);
    k_gemm<<<NIMG * 11, 224>>>(x);
    k_pixel<<<NPIX / 8, 256>>>();
    k_transpose<<<dim3(4, 2, BB * NYYC), dim3(32, 8)>>>(out);
}

// round 4
// speedup vs baseline: 3.1667x; 1.3507x over previous
#include <cuda_runtime.h>
#include <math.h>
#include <stdint.h>

typedef unsigned long long u64;
typedef unsigned int u32;

// ---------------- problem constants ----------------
#define BB   4
#define NNC  6
#define CINC 512
#define CTC  64
#define FHC  16
#define FWC  44
#define DDC  41
#define PPI  (FHC*FWC)          // 704
#define NIMG (BB*NNC)           // 24
#define NPIX (NIMG*PPI)         // 16896
#define MPAD 112
#define NXXC 128
#define NYYC 128

#define XS_LD 72                // Xs row pad (bank-distinct frag reads)
#define WS_LD 132               // Ws row pad (conflict-free vec4 reads)
#define GEMM_SMEM ((2*32*XS_LD + 2*32*WS_LD) * 4)   // 52224 bytes

// ---------------- scratch ----------------
__device__ __align__(16) float g_WdTp[512*128];     // [k][q*16+j], tf32-rounded, o=8j+q
__device__ __align__(16) float g_bias[112];
__device__ __align__(16) float g_mats[NIMG*24];
__device__ __align__(16) float g_feat[NPIX*MPAD];
__device__ __align__(16) float g_bev[BB*NYYC*NXXC*CTC];   // [b][y][x][c]

// ---------------- helpers ----------------
__device__ __forceinline__ void cpa16(uint32_t s, const void* g)
{
    asm volatile("cp.async.cg.shared.global [%0], [%1], 16;" :: "r"(s), "l"(g));
}
#define CP_COMMIT() asm volatile("cp.async.commit_group;")
#define CP_WAIT1()  asm volatile("cp.async.wait_group 1;")
#define CP_WAIT0()  asm volatile("cp.async.wait_group 0;")

__device__ __forceinline__ u32 f2tf32(float x)
{
    u32 r;
    asm("cvt.rna.tf32.f32 %0, %1;" : "=r"(r) : "f"(x));
    return r;
}

__device__ __forceinline__ void inv3(const float* a, float* r)
{
    float det = a[0]*(a[4]*a[8]-a[5]*a[7])
              - a[1]*(a[3]*a[8]-a[5]*a[6])
              + a[2]*(a[3]*a[7]-a[4]*a[6]);
    float id = 1.0f / det;
    r[0] = (a[4]*a[8]-a[5]*a[7])*id;
    r[1] = (a[2]*a[7]-a[1]*a[8])*id;
    r[2] = (a[1]*a[5]-a[2]*a[4])*id;
    r[3] = (a[5]*a[6]-a[3]*a[8])*id;
    r[4] = (a[0]*a[8]-a[2]*a[6])*id;
    r[5] = (a[2]*a[3]-a[0]*a[5])*id;
    r[6] = (a[3]*a[7]-a[4]*a[6])*id;
    r[7] = (a[1]*a[6]-a[0]*a[7])*id;
    r[8] = (a[0]*a[4]-a[1]*a[3])*id;
}

// ---------------- prep: zero BEV + WdTp (tf32, permuted) + per-image mats ----------
__global__ void k_prep(const float* __restrict__ Wd, const float* __restrict__ bd,
                       const float* __restrict__ rots, const float* __restrict__ trans,
                       const float* __restrict__ intrins, const float* __restrict__ post_rots,
                       const float* __restrict__ post_trans)
{
    int bi = blockIdx.x;
    int tid = threadIdx.x;
    if (bi < 4096) {                               // zero BEV
        reinterpret_cast<float4*>(g_bev)[bi * 256 + tid] = make_float4(0.f,0.f,0.f,0.f);
    } else if (bi < 4352) {                        // WdTp: 256*256 = 65536
        int idx = (bi - 4096) * 256 + tid;
        int k = idx >> 7, col = idx & 127;
        int q = col >> 4, jj = col & 15;
        int o = 8 * jj + q;
        float v = 0.f;
        if (jj < 14 && o < 105)
            v = __uint_as_float(f2tf32(Wd[o * 512 + k]));
        g_WdTp[idx] = v;
        if (idx < 112) g_bias[idx] = (idx < 105) ? bd[idx] : 0.f;
    } else {                                       // mats
        int bn = tid;
        if (bn >= NIMG) return;
        float P[9], Pi[9], K[9], Ki[9], R[9], C[9];
        #pragma unroll
        for (int i = 0; i < 9; i++) {
            P[i] = post_rots[bn*9 + i];
            K[i] = intrins[bn*9 + i];
            R[i] = rots[bn*9 + i];
        }
        inv3(P, Pi);
        inv3(K, Ki);
        #pragma unroll
        for (int i = 0; i < 3; i++)
            #pragma unroll
            for (int j = 0; j < 3; j++)
                C[i*3+j] = R[i*3+0]*Ki[0*3+j] + R[i*3+1]*Ki[1*3+j] + R[i*3+2]*Ki[2*3+j];
        float* m = &g_mats[bn*24];
        #pragma unroll
        for (int i = 0; i < 9; i++) { m[i] = Pi[i]; m[9+i] = C[i]; }
        #pragma unroll
        for (int i = 0; i < 3; i++) { m[18+i] = trans[bn*3+i]; m[21+i] = post_trans[bn*3+i]; }
    }
}

// ---------------- GEMM (tf32 mma.sync):  C[p][o] = sum_k X[k][p] * Wd[o][k] --------
// block 128 thr (4 warps). tile: 64 pixels (M) x 112 o (N). warp w: rows 16w..16w+15.
// A = X^T (frag reads from Xs[k][p]); B = WdTp (permuted, pre-tf32).
__global__ __launch_bounds__(128) void k_gemm(const float* __restrict__ x)
{
    extern __shared__ float smem[];
    float* Xs = smem;                       // [2][32][XS_LD]
    float* Ws = smem + 2*32*XS_LD;          // [2][32][WS_LD]

    int img = blockIdx.x / 11;
    int p0  = (blockIdx.x % 11) * 64;
    const float* Ximg = x + (size_t)img * CINC * PPI;

    int tid = threadIdx.x;
    int w   = tid >> 5;
    int lid = tid & 31;
    int qa  = lid >> 2;      // 0..7
    int ca  = lid & 3;       // 0..3

    uint32_t sX = (uint32_t)__cvta_generic_to_shared(Xs);
    uint32_t sW = (uint32_t)__cvta_generic_to_shared(Ws);

    float acc[14][4];
    #pragma unroll
    for (int j = 0; j < 14; j++)
        #pragma unroll
        for (int i = 0; i < 4; i++) acc[j][i] = 0.f;

    // prefetch chunk 0
    #pragma unroll
    for (int t = 0; t < 4; t++) {                 // X: 512 float4
        int i = tid + t * 128;
        int row = i >> 4, colv = i & 15;
        cpa16(sX + (uint32_t)((row * XS_LD + colv * 4) * 4),
              &Ximg[(size_t)row * PPI + p0 + colv * 4]);
    }
    #pragma unroll
    for (int t = 0; t < 8; t++) {                 // W: 1024 float4
        int i = tid + t * 128;
        int row = i >> 5, colv = i & 31;
        cpa16(sW + (uint32_t)((row * WS_LD + colv * 4) * 4),
              &g_WdTp[row * 128 + colv * 4]);
    }
    CP_COMMIT();

    for (int c = 0; c < 16; c++) {
        int buf = c & 1;
        if (c < 15) {
            int nb = (c + 1) & 1;
            int k0 = (c + 1) * 32;
            #pragma unroll
            for (int t = 0; t < 4; t++) {
                int i = tid + t * 128;
                int row = i >> 4, colv = i & 15;
                cpa16(sX + (uint32_t)(((nb*32 + row) * XS_LD + colv * 4) * 4),
                      &Ximg[(size_t)(k0 + row) * PPI + p0 + colv * 4]);
            }
            #pragma unroll
            for (int t = 0; t < 8; t++) {
                int i = tid + t * 128;
                int row = i >> 5, colv = i & 31;
                cpa16(sW + (uint32_t)(((nb*32 + row) * WS_LD + colv * 4) * 4),
                      &g_WdTp[(k0 + row) * 128 + colv * 4]);
            }
            CP_COMMIT();
            CP_WAIT1();
        } else {
            CP_WAIT0();
        }
        __syncthreads();

        const float* Xb = &Xs[buf * 32 * XS_LD];
        const float* Wb = &Ws[buf * 32 * WS_LD];

        #pragma unroll
        for (int s = 0; s < 4; s++) {
            // A fragments (convert f32 -> tf32 in regs)
            const float* xa = &Xb[(s*8 + ca) * XS_LD + 16*w + qa];
            u32 a0 = f2tf32(xa[0]);
            u32 a1 = f2tf32(xa[8]);
            u32 a2 = f2tf32(xa[4*XS_LD]);
            u32 a3 = f2tf32(xa[4*XS_LD + 8]);
            // B fragments: 16 contiguous pre-tf32 floats per k-row
            const uint4* wr0 = reinterpret_cast<const uint4*>(&Wb[(s*8 + ca) * WS_LD + qa*16]);
            const uint4* wr1 = reinterpret_cast<const uint4*>(&Wb[(s*8 + ca + 4) * WS_LD + qa*16]);
            u32 b0a[16], b1a[16];
            #pragma unroll
            for (int v = 0; v < 4; v++) {
                uint4 t0 = wr0[v], t1 = wr1[v];
                b0a[v*4+0]=t0.x; b0a[v*4+1]=t0.y; b0a[v*4+2]=t0.z; b0a[v*4+3]=t0.w;
                b1a[v*4+0]=t1.x; b1a[v*4+1]=t1.y; b1a[v*4+2]=t1.z; b1a[v*4+3]=t1.w;
            }
            #pragma unroll
            for (int j = 0; j < 14; j++) {
                asm volatile(
                    "mma.sync.aligned.m16n8k8.row.col.f32.tf32.tf32.f32 "
                    "{%0,%1,%2,%3}, {%4,%5,%6,%7}, {%8,%9}, {%0,%1,%2,%3};"
                    : "+f"(acc[j][0]), "+f"(acc[j][1]), "+f"(acc[j][2]), "+f"(acc[j][3])
                    : "r"(a0), "r"(a1), "r"(a2), "r"(a3), "r"(b0a[j]), "r"(b1a[j]));
            }
        }
        __syncthreads();
    }

    // epilogue: g_feat[p][o] = acc + bias
    {
        int p = img * PPI + p0 + 16*w + qa;
        #pragma unroll
        for (int j = 0; j < 14; j++) {
            int o = 8*j + 2*ca;
            float2 bs = *reinterpret_cast<const float2*>(&g_bias[o]);
            float2 v0 = make_float2(acc[j][0] + bs.x, acc[j][1] + bs.y);
            float2 v1 = make_float2(acc[j][2] + bs.x, acc[j][3] + bs.y);
            *reinterpret_cast<float2*>(&g_feat[(size_t)p * MPAD + o])       = v0;
            *reinterpret_cast<float2*>(&g_feat[(size_t)(p+8) * MPAD + o])   = v1;
        }
    }
}

// ---------------- fused pixel kernel: softmax + geometry + scatter ----------------
__global__ __launch_bounds__(256) void k_pixel()
{
    __shared__ float scvt[8][64];
    __shared__ float sdep[8][48];
    __shared__ int   svox[8][48];

    int wpb = threadIdx.x >> 5;
    int p = blockIdx.x * 8 + wpb;
    int l = threadIdx.x & 31;

    const float* f = &g_feat[(size_t)p * MPAD];

    float f0 = f[l];
    float f1 = (l < 9) ? f[32 + l] : -INFINITY;
    float m = fmaxf(f0, f1);
    #pragma unroll
    for (int o = 16; o; o >>= 1) m = fmaxf(m, __shfl_xor_sync(0xFFFFFFFFu, m, o));
    float e0 = __expf(f0 - m);
    float e1 = (l < 9) ? __expf(f1 - m) : 0.f;
    float s = e0 + e1;
    #pragma unroll
    for (int o = 16; o; o >>= 1) s += __shfl_xor_sync(0xFFFFFFFFu, s, o);
    float inv = 1.0f / s;
    float dep0 = e0 * inv;
    float dep1 = e1 * inv;

    scvt[wpb][l]      = f[DDC + l];
    scvt[wpb][32 + l] = f[DDC + 32 + l];

    int bn = p / PPI;
    int hw = p - bn * PPI;
    int h  = hw / FWC;
    int w  = hw - h * FWC;
    int b  = bn / NNC;

    const float* mm = &g_mats[bn * 24];
    float xs = (float)((double)w * (703.0 / 43.0));
    float ys = (float)h * 17.0f;

    float ax = xs - mm[21], ay = ys - mm[22];
    float qb0 = mm[0]*ax + mm[1]*ay;
    float qb1 = mm[3]*ax + mm[4]*ay;
    float qb2 = mm[6]*ax + mm[7]*ay;

    const float offx = -50.8f - 0.4f;
    const float offz = 0.0f - 10.0f;

    #pragma unroll
    for (int pass = 0; pass < 2; pass++) {
        int d = pass ? (32 + l) : l;
        if (pass && l >= 9) {
            if (l < 16) { svox[wpb][32 + l] = -1; sdep[wpb][32 + l] = 0.f; }
            break;
        }
        float az = (4.0f + (float)d) - mm[23];
        float q0 = qb0 + mm[2]*az;
        float q1 = qb1 + mm[5]*az;
        float q2 = qb2 + mm[8]*az;
        float r0 = q0 * q2, r1 = q1 * q2, r2 = q2;
        float wx = mm[9]*r0  + mm[10]*r1 + mm[11]*r2 + mm[18];
        float wy = mm[12]*r0 + mm[13]*r1 + mm[14]*r2 + mm[19];
        float wz = mm[15]*r0 + mm[16]*r1 + mm[17]*r2 + mm[20];
        int gx = (int)((wx - offx) / 0.8f);
        int gy = (int)((wy - offx) / 0.8f);
        int gz = (int)((wz - offz) / 20.0f);
        int vox = -1;
        if (gx >= 0 && gx < NXXC && gy >= 0 && gy < NYYC && gz == 0)
            vox = (b * NYYC + gy) * NXXC + gx;
        svox[wpb][d] = vox;
        sdep[wpb][d] = pass ? dep1 : dep0;
    }
    __syncwarp();

    float4 cv = *reinterpret_cast<float4*>(&scvt[wpb][(l & 15) << 2]);
    int half = l >> 4;
    #pragma unroll 4
    for (int it = 0; it < 21; it++) {
        int d = it * 2 + half;
        int vox = svox[wpb][d];
        if (vox >= 0) {
            float dep = sdep[wpb][d];
            float* dst = &g_bev[(size_t)vox * CTC + ((l & 15) << 2)];
            asm volatile("red.global.add.v4.f32 [%0], {%1, %2, %3, %4};"
                         :: "l"(dst), "f"(dep * cv.x), "f"(dep * cv.y),
                            "f"(dep * cv.z), "f"(dep * cv.w)
                         : "memory");
        }
    }
}

// ---------------- transpose [b][y][x][c] -> out [b][c][y][x] ----------------
__global__ void k_transpose(float* __restrict__ out)
{
    __shared__ float t[32][33];
    int x0 = blockIdx.x * 32;
    int c0 = blockIdx.y * 32;
    int by = blockIdx.z;
    int b  = by >> 7, y = by & 127;
    int tx = threadIdx.x, ty = threadIdx.y;

    const float* src = &g_bev[(size_t)by * NXXC * CTC];
    #pragma unroll
    for (int i = 0; i < 4; i++) {
        int xl = ty + i * 8;
        t[xl][tx] = src[(size_t)(x0 + xl) * CTC + c0 + tx];
    }
    __syncthreads();
    #pragma unroll
    for (int i = 0; i < 4; i++) {
        int cl = ty + i * 8;
        out[(((size_t)(b * CTC + c0 + cl) * NYYC) + y) * NXXC + x0 + tx] = t[tx][cl];
    }
}

// ---------------- launch ----------------
extern "C" void kernel_launch(void* const* d_in, const int* in_sizes, int n_in,
                              void* d_out, int out_size)
{
    const float* x          = (const float*)d_in[0];
    const float* rots       = (const float*)d_in[1];
    const float* trans      = (const float*)d_in[2];
    const float* intrins    = (const float*)d_in[3];
    const float* post_rots  = (const float*)d_in[4];
    const float* post_trans = (const float*)d_in[5];
    const float* Wd         = (const float*)d_in[6];
    const float* bd         = (const float*)d_in[7];
    float* out = (float*)d_out;

    cudaFuncSetAttribute(k_gemm, cudaFuncAttributeMaxDynamicSharedMemorySize, GEMM_SMEM);

    k_prep<<<4353, 256>>>(Wd, bd, rots, trans, intrins, post_rots, post_trans);
    k_gemm<<<NIMG * 11, 128, GEMM_SMEM>>>(x);
    k_pixel<<<NPIX / 8, 256>>>();
    k_transpose<<<dim3(4, 2, BB * NYYC), dim3(32, 8)>>>(out);
}